// round 3
// baseline (speedup 1.0000x reference)
#include <cuda_runtime.h>
#include <math.h>

#define N_TOK 65536
#define HDIM  1024
#define NEXP  3

#define BM 128
#define BN 64
#define BK 16

// ---- scratch (allocation-free: __device__ globals) ----
__device__ int   g_cursor[NEXP];
__device__ int   g_idx[NEXP * N_TOK];
__device__ float g_inner[(size_t)N_TOK * HDIM];   // 256 MiB

// ============================================================
// Kernel 0: zero per-expert cursors (must run every replay)
// ============================================================
__global__ void zero_kernel() {
    if (threadIdx.x < NEXP) g_cursor[threadIdx.x] = 0;
}

// ============================================================
// Kernel 1: gating. One warp per token.
// logits = x @ Wg + bg ; s = logits + gumbel(u) ; e* = argmax(s)
// Counting-sort token ids into per-expert lists.
// ============================================================
__global__ void gate_kernel(const float* __restrict__ x,
                            const float* __restrict__ Wg,
                            const float* __restrict__ bg,
                            const float* __restrict__ gu) {
    __shared__ float sWg[HDIM * NEXP];
    int tid = threadIdx.x;
    for (int t = tid; t < HDIM * NEXP; t += blockDim.x) sWg[t] = Wg[t];
    __syncthreads();

    int warp = tid >> 5, lane = tid & 31;
    int n = blockIdx.x * 8 + warp;
    const float* xr = x + (size_t)n * HDIM;

    float a0 = 0.f, a1 = 0.f, a2 = 0.f;
    #pragma unroll 8
    for (int j = 0; j < HDIM; j += 32) {
        float xi = xr[j + lane];
        const float* w = &sWg[(j + lane) * 3];
        a0 += xi * w[0];
        a1 += xi * w[1];
        a2 += xi * w[2];
    }
    #pragma unroll
    for (int off = 16; off > 0; off >>= 1) {
        a0 += __shfl_down_sync(0xffffffffu, a0, off);
        a1 += __shfl_down_sync(0xffffffffu, a1, off);
        a2 += __shfl_down_sync(0xffffffffu, a2, off);
    }
    if (lane == 0) {
        float s[3];
        s[0] = a0 + bg[0];
        s[1] = a1 + bg[1];
        s[2] = a2 + bg[2];
        #pragma unroll
        for (int e = 0; e < 3; e++) {
            float u = gu[(size_t)n * 3 + e];
            u = fminf(fmaxf(u, 1e-6f), 1.0f - 1e-6f);
            s[e] += -logf(-logf(u));
        }
        // argmax with first-index-on-tie (strict >)
        int best = 0;
        if (s[1] > s[best]) best = 1;
        if (s[2] > s[best]) best = 2;
        int pos = atomicAdd(&g_cursor[best], 1);
        g_idx[best * N_TOK + pos] = n;
    }
}

// ============================================================
// Kernel 2: Pass A — grouped dual GEMM + activation epilogue.
// For expert e, gathered rows: H1 = X@W1[e]+b1, H3 = X@W3[e]+b3,
// inner = act_e(H1) * H3  -> g_inner at sorted positions.
// grid: (HDIM/BN, N_TOK/BM, NEXP)
// ============================================================
__global__ __launch_bounds__(256)
void passA_kernel(const float* __restrict__ x,
                  const float* __restrict__ W1,
                  const float* __restrict__ b1,
                  const float* __restrict__ W3,
                  const float* __restrict__ b3) {
    int e    = blockIdx.z;
    int cnt  = g_cursor[e];
    int base = blockIdx.y * BM;
    if (base >= cnt) return;
    int n0  = blockIdx.x * BN;
    int tid = threadIdx.x;

    int off = 0;
    #pragma unroll
    for (int i = 0; i < NEXP; i++) if (i < e) off += g_cursor[i];

    __shared__ float Xs[BK][BM];
    __shared__ float W1s[BK][BN];
    __shared__ float W3s[BK][BN];
    __shared__ int   srow[BM];

    if (tid < BM) {
        int p = base + tid;
        srow[tid] = (p < cnt) ? g_idx[e * N_TOK + p] : 0;
    }
    __syncthreads();

    const float* W1e = W1 + (size_t)e * HDIM * HDIM;
    const float* W3e = W3 + (size_t)e * HDIM * HDIM;

    int r    = tid >> 1;           // 0..127 : X row within tile
    int seg  = (tid & 1) * 8;      // 0 or 8 : k-segment
    int krow = tid >> 4;           // 0..15  : W row within k-tile
    int col4 = (tid & 15) * 4;     // 0..60  : W col (x4)
    int tx   = tid & 15;           // micro-tile n
    int ty   = tid >> 4;           // micro-tile m

    const float* xrow = x + (size_t)srow[r] * HDIM;

    float acc1[8][4];
    float acc3[8][4];
    #pragma unroll
    for (int i = 0; i < 8; i++)
        #pragma unroll
        for (int j = 0; j < 4; j++) { acc1[i][j] = 0.f; acc3[i][j] = 0.f; }

    for (int k0 = 0; k0 < HDIM; k0 += BK) {
        float4 xa = *(const float4*)(xrow + k0 + seg);
        float4 xb = *(const float4*)(xrow + k0 + seg + 4);
        float4 w1v = *(const float4*)(W1e + (size_t)(k0 + krow) * HDIM + n0 + col4);
        float4 w3v = *(const float4*)(W3e + (size_t)(k0 + krow) * HDIM + n0 + col4);

        __syncthreads();
        Xs[seg + 0][r] = xa.x; Xs[seg + 1][r] = xa.y;
        Xs[seg + 2][r] = xa.z; Xs[seg + 3][r] = xa.w;
        Xs[seg + 4][r] = xb.x; Xs[seg + 5][r] = xb.y;
        Xs[seg + 6][r] = xb.z; Xs[seg + 7][r] = xb.w;
        *(float4*)&W1s[krow][col4] = w1v;
        *(float4*)&W3s[krow][col4] = w3v;
        __syncthreads();

        #pragma unroll
        for (int kk = 0; kk < BK; kk++) {
            float4 A0 = *(float4*)&Xs[kk][ty * 8];
            float4 A1 = *(float4*)&Xs[kk][ty * 8 + 4];
            float4 B1 = *(float4*)&W1s[kk][tx * 4];
            float4 B3 = *(float4*)&W3s[kk][tx * 4];
            float a[8] = {A0.x, A0.y, A0.z, A0.w, A1.x, A1.y, A1.z, A1.w};
            float c1[4] = {B1.x, B1.y, B1.z, B1.w};
            float c3[4] = {B3.x, B3.y, B3.z, B3.w};
            #pragma unroll
            for (int i = 0; i < 8; i++)
                #pragma unroll
                for (int j = 0; j < 4; j++) {
                    acc1[i][j] += a[i] * c1[j];
                    acc3[i][j] += a[i] * c3[j];
                }
        }
    }

    int mrows = cnt - base;
    if (mrows > BM) mrows = BM;
    float* outbase = g_inner + (size_t)(off + base) * HDIM;

    #pragma unroll
    for (int i = 0; i < 8; i++) {
        int m = ty * 8 + i;
        if (m >= mrows) continue;
        int nn = n0 + tx * 4;
        float4 o;
        float v[4];
        #pragma unroll
        for (int j = 0; j < 4; j++) {
            float h1 = acc1[i][j] + b1[e * HDIM + nn + j];
            float h3 = acc3[i][j] + b3[e * HDIM + nn + j];
            float a;
            if (e == 0)      a = h1 / (1.0f + expf(-h1));                       // SiLU
            else if (e == 1) a = 0.5f * h1 * (1.0f + erff(h1 * 0.70710678118654752f)); // exact GELU
            else             a = fmaxf(h1, 0.0f);                               // ReLU
            v[j] = a * h3;
        }
        o.x = v[0]; o.y = v[1]; o.z = v[2]; o.w = v[3];
        *(float4*)(outbase + (size_t)m * HDIM + nn) = o;
    }
}

// ============================================================
// Kernel 3: Pass B — grouped GEMM inner@W2[e]+b2, scatter to out
// grid: (HDIM/BN, N_TOK/BM, NEXP)
// ============================================================
__global__ __launch_bounds__(256)
void passB_kernel(const float* __restrict__ W2,
                  const float* __restrict__ b2,
                  float* __restrict__ out) {
    int e    = blockIdx.z;
    int cnt  = g_cursor[e];
    int base = blockIdx.y * BM;
    if (base >= cnt) return;
    int n0  = blockIdx.x * BN;
    int tid = threadIdx.x;

    int off = 0;
    #pragma unroll
    for (int i = 0; i < NEXP; i++) if (i < e) off += g_cursor[i];

    __shared__ float Xs[BK][BM];
    __shared__ float W2s[BK][BN];
    __shared__ int   stok[BM];

    if (tid < BM) {
        int p = base + tid;
        stok[tid] = (p < cnt) ? g_idx[e * N_TOK + p] : 0;
    }
    __syncthreads();

    const float* W2e = W2 + (size_t)e * HDIM * HDIM;

    int r    = tid >> 1;
    int seg  = (tid & 1) * 8;
    int krow = tid >> 4;
    int col4 = (tid & 15) * 4;
    int tx   = tid & 15;
    int ty   = tid >> 4;

    int prow = off + base + r;
    if (base + r >= cnt) prow = off;   // clamp to a valid row for padded lanes
    const float* xrow = g_inner + (size_t)prow * HDIM;

    float acc[8][4];
    #pragma unroll
    for (int i = 0; i < 8; i++)
        #pragma unroll
        for (int j = 0; j < 4; j++) acc[i][j] = 0.f;

    for (int k0 = 0; k0 < HDIM; k0 += BK) {
        float4 xa = *(const float4*)(xrow + k0 + seg);
        float4 xb = *(const float4*)(xrow + k0 + seg + 4);
        float4 w2v = *(const float4*)(W2e + (size_t)(k0 + krow) * HDIM + n0 + col4);

        __syncthreads();
        Xs[seg + 0][r] = xa.x; Xs[seg + 1][r] = xa.y;
        Xs[seg + 2][r] = xa.z; Xs[seg + 3][r] = xa.w;
        Xs[seg + 4][r] = xb.x; Xs[seg + 5][r] = xb.y;
        Xs[seg + 6][r] = xb.z; Xs[seg + 7][r] = xb.w;
        *(float4*)&W2s[krow][col4] = w2v;
        __syncthreads();

        #pragma unroll
        for (int kk = 0; kk < BK; kk++) {
            float4 A0 = *(float4*)&Xs[kk][ty * 8];
            float4 A1 = *(float4*)&Xs[kk][ty * 8 + 4];
            float4 B  = *(float4*)&W2s[kk][tx * 4];
            float a[8] = {A0.x, A0.y, A0.z, A0.w, A1.x, A1.y, A1.z, A1.w};
            float c[4] = {B.x, B.y, B.z, B.w};
            #pragma unroll
            for (int i = 0; i < 8; i++)
                #pragma unroll
                for (int j = 0; j < 4; j++)
                    acc[i][j] += a[i] * c[j];
        }
    }

    int mrows = cnt - base;
    if (mrows > BM) mrows = BM;

    #pragma unroll
    for (int i = 0; i < 8; i++) {
        int m = ty * 8 + i;
        if (m >= mrows) continue;
        int tok = stok[m];
        int nn = n0 + tx * 4;
        float4 o;
        o.x = acc[i][0] + b2[e * HDIM + nn + 0];
        o.y = acc[i][1] + b2[e * HDIM + nn + 1];
        o.z = acc[i][2] + b2[e * HDIM + nn + 2];
        o.w = acc[i][3] + b2[e * HDIM + nn + 3];
        *(float4*)(out + (size_t)tok * HDIM + nn) = o;
    }
}

// ============================================================
extern "C" void kernel_launch(void* const* d_in, const int* in_sizes, int n_in,
                              void* d_out, int out_size) {
    (void)in_sizes; (void)n_in; (void)out_size;
    const float* x  = (const float*)d_in[0];
    const float* W1 = (const float*)d_in[1];
    const float* b1 = (const float*)d_in[2];
    const float* W2 = (const float*)d_in[3];
    const float* b2 = (const float*)d_in[4];
    const float* W3 = (const float*)d_in[5];
    const float* b3 = (const float*)d_in[6];
    const float* Wg = (const float*)d_in[7];
    const float* bg = (const float*)d_in[8];
    const float* gu = (const float*)d_in[9];
    float* out = (float*)d_out;

    zero_kernel<<<1, 32>>>();
    gate_kernel<<<N_TOK / 8, 256>>>(x, Wg, bg, gu);

    dim3 grid(HDIM / BN, N_TOK / BM, NEXP);
    passA_kernel<<<grid, 256>>>(x, W1, b1, W3, b3);
    passB_kernel<<<grid, 256>>>(W2, b2, out);
}

// round 5
// speedup vs baseline: 1.4968x; 1.4968x over previous
#include <cuda_runtime.h>
#include <cuda_bf16.h>
#include <math.h>
#include <stdint.h>

#define N_TOK 65536
#define HDIM  1024
#define NEXP  3
#define NCH   48          // 3*1024/64 : K-concat chunks (hi*hi, lo*hi, hi*lo)
#define BM    128
#define BN    128

typedef __nv_bfloat16 bf16;

// ------------------- scratch (allocation-free) -------------------
__device__ int  g_cursor[NEXP];
__device__ int  g_idx[NEXP * N_TOK];
__device__ bf16 g_xhi[(size_t)N_TOK * HDIM];
__device__ bf16 g_xlo[(size_t)N_TOK * HDIM];
__device__ bf16 g_ihi[(size_t)N_TOK * HDIM];
__device__ bf16 g_ilo[(size_t)N_TOK * HDIM];
__device__ bf16 g_w1hi[(size_t)NEXP * HDIM * HDIM];
__device__ bf16 g_w1lo[(size_t)NEXP * HDIM * HDIM];
__device__ bf16 g_w3hi[(size_t)NEXP * HDIM * HDIM];
__device__ bf16 g_w3lo[(size_t)NEXP * HDIM * HDIM];
__device__ bf16 g_w2hi[(size_t)NEXP * HDIM * HDIM];
__device__ bf16 g_w2lo[(size_t)NEXP * HDIM * HDIM];

// ------------------- helpers -------------------
__device__ __forceinline__ uint32_t s2u(const void* p) {
    return (uint32_t)__cvta_generic_to_shared(p);
}
__device__ __forceinline__ void cp16(uint32_t dst, const void* src) {
    asm volatile("cp.async.cg.shared.global [%0], [%1], 16;" :: "r"(dst), "l"(src));
}
#define CP_COMMIT() asm volatile("cp.async.commit_group;" ::: "memory")
#define CP_WAIT(n)  asm volatile("cp.async.wait_group %0;" :: "n"(n) : "memory")

#define LDSM4(r0,r1,r2,r3,addr) \
    asm volatile("ldmatrix.sync.aligned.m8n8.x4.shared.b16 {%0,%1,%2,%3}, [%4];" \
        : "=r"(r0), "=r"(r1), "=r"(r2), "=r"(r3) : "r"(addr))

#define MMA16816(d, a0,a1,a2,a3, b0,b1) \
    asm volatile("mma.sync.aligned.m16n8k16.row.col.f32.bf16.bf16.f32 " \
        "{%0,%1,%2,%3}, {%4,%5,%6,%7}, {%8,%9}, {%0,%1,%2,%3};" \
        : "+f"((d)[0]), "+f"((d)[1]), "+f"((d)[2]), "+f"((d)[3]) \
        : "r"(a0), "r"(a1), "r"(a2), "r"(a3), "r"(b0), "r"(b1))

__device__ __forceinline__ uint32_t swz(uint32_t o) { return o ^ ((o >> 3) & 0x70); }

__device__ __forceinline__ float act_fn(float h1, int e) {
    if (e == 0) return h1 / (1.0f + expf(-h1));
    if (e == 1) return 0.5f * h1 * (1.0f + erff(h1 * 0.70710678118654752f));
    return fmaxf(h1, 0.0f);
}
__device__ __forceinline__ uint32_t pack_bf2(float a, float b) {
    __nv_bfloat162 t = __halves2bfloat162(__float2bfloat16_rn(a), __float2bfloat16_rn(b));
    return *(uint32_t*)&t;
}

// ============================================================
// Kernel 0: zero per-expert cursors
// ============================================================
__global__ void zero_kernel() {
    if (threadIdx.x < NEXP) g_cursor[threadIdx.x] = 0;
}

// ============================================================
// Kernel 1: gating (one warp per token)
// ============================================================
__global__ void gate_kernel(const float* __restrict__ x,
                            const float* __restrict__ Wg,
                            const float* __restrict__ bg,
                            const float* __restrict__ gu) {
    __shared__ float sWg[HDIM * NEXP];
    int tid = threadIdx.x;
    for (int t = tid; t < HDIM * NEXP; t += blockDim.x) sWg[t] = Wg[t];
    __syncthreads();

    int warp = tid >> 5, lane = tid & 31;
    int n = blockIdx.x * 8 + warp;
    const float* xr = x + (size_t)n * HDIM;

    float a0 = 0.f, a1 = 0.f, a2 = 0.f;
    #pragma unroll 8
    for (int j = 0; j < HDIM; j += 32) {
        float xi = xr[j + lane];
        const float* w = &sWg[(j + lane) * 3];
        a0 += xi * w[0];
        a1 += xi * w[1];
        a2 += xi * w[2];
    }
    #pragma unroll
    for (int off = 16; off > 0; off >>= 1) {
        a0 += __shfl_down_sync(0xffffffffu, a0, off);
        a1 += __shfl_down_sync(0xffffffffu, a1, off);
        a2 += __shfl_down_sync(0xffffffffu, a2, off);
    }
    if (lane == 0) {
        float s[3];
        s[0] = a0 + bg[0];
        s[1] = a1 + bg[1];
        s[2] = a2 + bg[2];
        #pragma unroll
        for (int e = 0; e < 3; e++) {
            float u = gu[(size_t)n * 3 + e];
            u = fminf(fmaxf(u, 1e-6f), 1.0f - 1e-6f);
            s[e] += -logf(-logf(u));
        }
        int best = 0;
        if (s[1] > s[best]) best = 1;
        if (s[2] > s[best]) best = 2;
        int pos = atomicAdd(&g_cursor[best], 1);
        g_idx[best * N_TOK + pos] = n;
    }
}

// ============================================================
// Kernel 2: split x into bf16 hi/lo
// ============================================================
__global__ void xsplit_kernel(const float* __restrict__ x) {
    size_t i = ((size_t)blockIdx.x * 256 + threadIdx.x) * 4;
    float4 v = *(const float4*)(x + i);
    bf16 h0 = __float2bfloat16_rn(v.x);
    bf16 h1 = __float2bfloat16_rn(v.y);
    bf16 h2 = __float2bfloat16_rn(v.z);
    bf16 h3 = __float2bfloat16_rn(v.w);
    bf16 l0 = __float2bfloat16_rn(v.x - __bfloat162float(h0));
    bf16 l1 = __float2bfloat16_rn(v.y - __bfloat162float(h1));
    bf16 l2 = __float2bfloat16_rn(v.z - __bfloat162float(h2));
    bf16 l3 = __float2bfloat16_rn(v.w - __bfloat162float(h3));
    __nv_bfloat162 ha = __halves2bfloat162(h0, h1), hb = __halves2bfloat162(h2, h3);
    __nv_bfloat162 la = __halves2bfloat162(l0, l1), lb = __halves2bfloat162(l2, l3);
    uint2 hq = make_uint2(*(uint32_t*)&ha, *(uint32_t*)&hb);
    uint2 lq = make_uint2(*(uint32_t*)&la, *(uint32_t*)&lb);
    *(uint2*)(g_xhi + i) = hq;
    *(uint2*)(g_xlo + i) = lq;
}

// ============================================================
// Kernel 3: transpose + split weights -> K-major bf16 hi/lo
//   grid (32, 32, 9): z = mat*3 + e ; mat: 0=W1, 1=W3, 2=W2
// ============================================================
__global__ void wsplit_kernel(const float* __restrict__ W1,
                              const float* __restrict__ W3,
                              const float* __restrict__ W2) {
    __shared__ float t[32][33];
    int z = blockIdx.z;
    int mat = z / 3, e = z % 3;
    const float* src;
    bf16 *dh, *dl;
    if (mat == 0)      { src = W1; dh = g_w1hi; dl = g_w1lo; }
    else if (mat == 1) { src = W3; dh = g_w3hi; dl = g_w3lo; }
    else               { src = W2; dh = g_w2hi; dl = g_w2lo; }
    size_t eo = (size_t)e * HDIM * HDIM;
    src += eo; dh += eo; dl += eo;

    int bx = blockIdx.x * 32, by = blockIdx.y * 32;
    int tx = threadIdx.x;
    for (int i = threadIdx.y; i < 32; i += 8)
        t[i][tx] = src[(size_t)(by + i) * HDIM + bx + tx];
    __syncthreads();
    for (int i = threadIdx.y; i < 32; i += 8) {
        float v = t[tx][i];                              // = W[by+tx][bx+i]
        size_t di = (size_t)(bx + i) * HDIM + by + tx;   // Wt[h][d]
        bf16 h = __float2bfloat16_rn(v);
        dh[di] = h;
        dl[di] = __float2bfloat16_rn(v - __bfloat162float(h));
    }
}

// ============================================================
// Kernel 4: pass A — mma.sync dual GEMM (h1, h3) + activation
//   256 threads (8 warps, 4m x 2n), tile 128x128, BK=64,
//   3-stage cp.async. grid (8, 512, 3)
// ============================================================
#define A_STAGE 49152
#define A_SMEM  (2048 + 3 * A_STAGE)

__global__ __launch_bounds__(256, 1)
void passA_mma(const float* __restrict__ b1, const float* __restrict__ b3) {
    int e    = blockIdx.z;
    int cnt  = g_cursor[e];
    int base = blockIdx.y * BM;
    if (base >= cnt) return;
    int n0  = blockIdx.x * BN;
    int tid = threadIdx.x, wid = tid >> 5, lane = tid & 31;
    int m32 = (wid & 3) * 32;        // warp m offset
    int n64 = (wid >> 2) * 64;       // warp n offset

    extern __shared__ char smem[];
    uint32_t sb = s2u(smem);

    int off = 0;
    for (int i = 0; i < e; i++) off += g_cursor[i];

    int*   srow = (int*)(smem);
    float* sb1  = (float*)(smem + 512);
    float* sb3  = (float*)(smem + 1024);
    if (tid < BM) {
        int p = base + tid;
        srow[tid] = (p < cnt) ? g_idx[e * N_TOK + p] : g_idx[e * N_TOK];
        sb1[tid]  = b1[e * HDIM + n0 + tid];
        sb3[tid]  = b3[e * HDIM + n0 + tid];
    }
    __syncthreads();

    const bf16* w1h = g_w1hi + (size_t)e * HDIM * HDIM;
    const bf16* w1l = g_w1lo + (size_t)e * HDIM * HDIM;
    const bf16* w3h = g_w3hi + (size_t)e * HDIM * HDIM;
    const bf16* w3l = g_w3lo + (size_t)e * HDIM * HDIM;

    auto load_chunk = [&](int c) {
        int st  = c % 3;
        int kk0 = (c & 15) << 6;
        const bf16* As  = (c >= 16 && c < 32) ? g_xlo : g_xhi;
        const bf16* B1s = (c < 32) ? w1h : w1l;
        const bf16* B3s = (c < 32) ? w3h : w3l;
        uint32_t sa = sb + 2048 + st * A_STAGE;
        #pragma unroll
        for (int it = 0; it < 4; it++) {
            int g = tid + it * 256;
            int row = g >> 3, c16 = g & 7;
            uint32_t sw = swz((uint32_t)((row << 7) | (c16 << 4)));
            int col = kk0 + (c16 << 3);
            cp16(sa + sw,         As  + (size_t)srow[row] * HDIM + col);
            cp16(sa + 16384 + sw, B1s + (size_t)(n0 + row) * HDIM + col);
            cp16(sa + 32768 + sw, B3s + (size_t)(n0 + row) * HDIM + col);
        }
        CP_COMMIT();
    };

    float acc1[2][8][4];
    float acc3[2][8][4];
    #pragma unroll
    for (int i = 0; i < 2; i++)
        #pragma unroll
        for (int j = 0; j < 8; j++)
            #pragma unroll
            for (int q = 0; q < 4; q++) { acc1[i][j][q] = 0.f; acc3[i][j][q] = 0.f; }

    load_chunk(0); load_chunk(1);

    for (int c = 0; c < NCH; c++) {
        CP_WAIT(1);
        __syncthreads();
        uint32_t sa = sb + 2048 + (c % 3) * A_STAGE;
        #pragma unroll
        for (int kk = 0; kk < 4; kk++) {
            uint32_t a[2][4];
            #pragma unroll
            for (int i = 0; i < 2; i++) {
                int row = m32 + i * 16 + (lane & 15);
                uint32_t o = (uint32_t)(row * 128 + (kk * 2 + (lane >> 4)) * 16);
                LDSM4(a[i][0], a[i][1], a[i][2], a[i][3], sa + swz(o));
            }
            #pragma unroll
            for (int j = 0; j < 4; j++) {
                int nrow = n64 + j * 16 + ((lane >> 4) << 3) + (lane & 7);
                int half = (lane >> 3) & 1;
                uint32_t o = (uint32_t)(nrow * 128 + (kk * 2 + half) * 16);
                uint32_t sw = swz(o);
                uint32_t b0, b1r, b2, b3r;
                LDSM4(b0, b1r, b2, b3r, sa + 16384 + sw);
                #pragma unroll
                for (int i = 0; i < 2; i++) {
                    MMA16816(acc1[i][2*j],   a[i][0], a[i][1], a[i][2], a[i][3], b0, b1r);
                    MMA16816(acc1[i][2*j+1], a[i][0], a[i][1], a[i][2], a[i][3], b2, b3r);
                }
                LDSM4(b0, b1r, b2, b3r, sa + 32768 + sw);
                #pragma unroll
                for (int i = 0; i < 2; i++) {
                    MMA16816(acc3[i][2*j],   a[i][0], a[i][1], a[i][2], a[i][3], b0, b1r);
                    MMA16816(acc3[i][2*j+1], a[i][0], a[i][1], a[i][2], a[i][3], b2, b3r);
                }
            }
        }
        __syncthreads();
        if (c + 2 < NCH) load_chunk(c + 2);
    }

    // epilogue: bias + activation, split-bf16 store of inner
    int mrows = cnt - base; if (mrows > BM) mrows = BM;
    #pragma unroll
    for (int i = 0; i < 2; i++) {
        int r0 = m32 + i * 16 + (lane >> 2);
        int r1 = r0 + 8;
        size_t g0 = (size_t)(off + base + r0) * HDIM;
        size_t g1 = (size_t)(off + base + r1) * HDIM;
        #pragma unroll
        for (int j = 0; j < 8; j++) {
            int n = n64 + j * 8 + (lane & 3) * 2;
            float bb1a = sb1[n], bb1b = sb1[n + 1];
            float bb3a = sb3[n], bb3b = sb3[n + 1];
            if (r0 < mrows) {
                float v0 = act_fn(acc1[i][j][0] + bb1a, e) * (acc3[i][j][0] + bb3a);
                float v1 = act_fn(acc1[i][j][1] + bb1b, e) * (acc3[i][j][1] + bb3b);
                bf16 h0 = __float2bfloat16_rn(v0), h1 = __float2bfloat16_rn(v1);
                *(uint32_t*)(g_ihi + g0 + n0 + n) = pack_bf2(v0, v1);
                *(uint32_t*)(g_ilo + g0 + n0 + n) =
                    pack_bf2(v0 - __bfloat162float(h0), v1 - __bfloat162float(h1));
            }
            if (r1 < mrows) {
                float v2 = act_fn(acc1[i][j][2] + bb1a, e) * (acc3[i][j][2] + bb3a);
                float v3 = act_fn(acc1[i][j][3] + bb1b, e) * (acc3[i][j][3] + bb3b);
                bf16 h2 = __float2bfloat16_rn(v2), h3 = __float2bfloat16_rn(v3);
                *(uint32_t*)(g_ihi + g1 + n0 + n) = pack_bf2(v2, v3);
                *(uint32_t*)(g_ilo + g1 + n0 + n) =
                    pack_bf2(v2 - __bfloat162float(h2), v3 - __bfloat162float(h3));
            }
        }
    }
}

// ============================================================
// Kernel 5: pass B — mma.sync GEMM inner@W2 + b2, scatter
//   grid (8, 512, 3)
// ============================================================
#define B_STAGE 32768
#define B_SMEM  (2048 + 3 * B_STAGE)

__global__ __launch_bounds__(256, 1)
void passB_mma(const float* __restrict__ b2, float* __restrict__ out) {
    int e    = blockIdx.z;
    int cnt  = g_cursor[e];
    int base = blockIdx.y * BM;
    if (base >= cnt) return;
    int n0  = blockIdx.x * BN;
    int tid = threadIdx.x, wid = tid >> 5, lane = tid & 31;
    int m32 = (wid & 3) * 32;
    int n64 = (wid >> 2) * 64;

    extern __shared__ char smem[];
    uint32_t sb = s2u(smem);

    int off = 0;
    for (int i = 0; i < e; i++) off += g_cursor[i];

    int*   stok = (int*)(smem);
    float* sb2  = (float*)(smem + 512);
    if (tid < BM) {
        int p = base + tid;
        stok[tid] = (p < cnt) ? g_idx[e * N_TOK + p] : 0;
        sb2[tid]  = b2[e * HDIM + n0 + tid];
    }
    __syncthreads();

    const bf16* w2h = g_w2hi + (size_t)e * HDIM * HDIM;
    const bf16* w2l = g_w2lo + (size_t)e * HDIM * HDIM;

    auto load_chunk = [&](int c) {
        int st  = c % 3;
        int kk0 = (c & 15) << 6;
        const bf16* As = (c >= 16 && c < 32) ? g_ilo : g_ihi;
        const bf16* Bs = (c < 32) ? w2h : w2l;
        uint32_t sa = sb + 2048 + st * B_STAGE;
        #pragma unroll
        for (int it = 0; it < 4; it++) {
            int g = tid + it * 256;
            int row = g >> 3, c16 = g & 7;
            uint32_t sw = swz((uint32_t)((row << 7) | (c16 << 4)));
            int col = kk0 + (c16 << 3);
            int arow = (base + row < cnt) ? (off + base + row) : off;
            cp16(sa + sw,         As + (size_t)arow * HDIM + col);
            cp16(sa + 16384 + sw, Bs + (size_t)(n0 + row) * HDIM + col);
        }
        CP_COMMIT();
    };

    float acc[2][8][4];
    #pragma unroll
    for (int i = 0; i < 2; i++)
        #pragma unroll
        for (int j = 0; j < 8; j++)
            #pragma unroll
            for (int q = 0; q < 4; q++) acc[i][j][q] = 0.f;

    load_chunk(0); load_chunk(1);

    for (int c = 0; c < NCH; c++) {
        CP_WAIT(1);
        __syncthreads();
        uint32_t sa = sb + 2048 + (c % 3) * B_STAGE;
        #pragma unroll
        for (int kk = 0; kk < 4; kk++) {
            uint32_t a[2][4];
            #pragma unroll
            for (int i = 0; i < 2; i++) {
                int row = m32 + i * 16 + (lane & 15);
                uint32_t o = (uint32_t)(row * 128 + (kk * 2 + (lane >> 4)) * 16);
                LDSM4(a[i][0], a[i][1], a[i][2], a[i][3], sa + swz(o));
            }
            #pragma unroll
            for (int j = 0; j < 4; j++) {
                int nrow = n64 + j * 16 + ((lane >> 4) << 3) + (lane & 7);
                int half = (lane >> 3) & 1;
                uint32_t o = (uint32_t)(nrow * 128 + (kk * 2 + half) * 16);
                uint32_t b0, b1r, b2r, b3r;
                LDSM4(b0, b1r, b2r, b3r, sa + 16384 + swz(o));
                #pragma unroll
                for (int i = 0; i < 2; i++) {
                    MMA16816(acc[i][2*j],   a[i][0], a[i][1], a[i][2], a[i][3], b0, b1r);
                    MMA16816(acc[i][2*j+1], a[i][0], a[i][1], a[i][2], a[i][3], b2r, b3r);
                }
            }
        }
        __syncthreads();
        if (c + 2 < NCH) load_chunk(c + 2);
    }

    int mrows = cnt - base; if (mrows > BM) mrows = BM;
    #pragma unroll
    for (int i = 0; i < 2; i++) {
        int r0 = m32 + i * 16 + (lane >> 2);
        int r1 = r0 + 8;
        float* d0 = out + (size_t)stok[r0 < BM ? r0 : 0] * HDIM + n0;
        float* d1 = out + (size_t)stok[r1 < BM ? r1 : 0] * HDIM + n0;
        #pragma unroll
        for (int j = 0; j < 8; j++) {
            int n = n64 + j * 8 + (lane & 3) * 2;
            float ba = sb2[n], bb = sb2[n + 1];
            if (r0 < mrows) {
                float2 o0 = make_float2(acc[i][j][0] + ba, acc[i][j][1] + bb);
                *(float2*)(d0 + n) = o0;
            }
            if (r1 < mrows) {
                float2 o1 = make_float2(acc[i][j][2] + ba, acc[i][j][3] + bb);
                *(float2*)(d1 + n) = o1;
            }
        }
    }
}

// ============================================================
extern "C" void kernel_launch(void* const* d_in, const int* in_sizes, int n_in,
                              void* d_out, int out_size) {
    (void)in_sizes; (void)n_in; (void)out_size;
    const float* x  = (const float*)d_in[0];
    const float* W1 = (const float*)d_in[1];
    const float* b1 = (const float*)d_in[2];
    const float* W2 = (const float*)d_in[3];
    const float* b2 = (const float*)d_in[4];
    const float* W3 = (const float*)d_in[5];
    const float* b3 = (const float*)d_in[6];
    const float* Wg = (const float*)d_in[7];
    const float* bg = (const float*)d_in[8];
    const float* gu = (const float*)d_in[9];
    float* out = (float*)d_out;

    cudaFuncSetAttribute(passA_mma, cudaFuncAttributeMaxDynamicSharedMemorySize, A_SMEM);
    cudaFuncSetAttribute(passB_mma, cudaFuncAttributeMaxDynamicSharedMemorySize, B_SMEM);

    zero_kernel<<<1, 32>>>();
    gate_kernel<<<N_TOK / 8, 256>>>(x, Wg, bg, gu);
    xsplit_kernel<<<(int)(((size_t)N_TOK * HDIM) / 1024), 256>>>(x);
    {
        dim3 g(32, 32, 9), b(32, 8);
        wsplit_kernel<<<g, b>>>(W1, W3, W2);
    }
    {
        dim3 grid(HDIM / BN, N_TOK / BM, NEXP);
        passA_mma<<<grid, 256, A_SMEM>>>(b1, b3);
        passB_mma<<<grid, 256, B_SMEM>>>(b2, out);
    }
}

// round 6
// speedup vs baseline: 2.4046x; 1.6065x over previous
#include <cuda_runtime.h>
#include <cuda_bf16.h>
#include <math.h>
#include <stdint.h>

#define N_TOK 65536
#define HDIM  1024
#define NEXP  3
#define NCH   48          // 3*1024/64 : K-concat chunks (hi*hi, lo*hi, hi*lo)
#define BM    128
#define BN    128

typedef __nv_bfloat16 bf16;

// ------------------- scratch (allocation-free) -------------------
__device__ int  g_cursor[NEXP];
__device__ int  g_idx[NEXP * N_TOK];
__device__ bf16 g_xhi[(size_t)N_TOK * HDIM];
__device__ bf16 g_xlo[(size_t)N_TOK * HDIM];
__device__ bf16 g_ihi[(size_t)N_TOK * HDIM];
__device__ bf16 g_ilo[(size_t)N_TOK * HDIM];
__device__ bf16 g_w1hi[(size_t)NEXP * HDIM * HDIM];
__device__ bf16 g_w1lo[(size_t)NEXP * HDIM * HDIM];
__device__ bf16 g_w3hi[(size_t)NEXP * HDIM * HDIM];
__device__ bf16 g_w3lo[(size_t)NEXP * HDIM * HDIM];
__device__ bf16 g_w2hi[(size_t)NEXP * HDIM * HDIM];
__device__ bf16 g_w2lo[(size_t)NEXP * HDIM * HDIM];

// ------------------- helpers -------------------
__device__ __forceinline__ uint32_t s2u(const void* p) {
    return (uint32_t)__cvta_generic_to_shared(p);
}
__device__ __forceinline__ void cp16(uint32_t dst, const void* src) {
    asm volatile("cp.async.cg.shared.global [%0], [%1], 16;" :: "r"(dst), "l"(src));
}
#define CP_COMMIT() asm volatile("cp.async.commit_group;" ::: "memory")
#define CP_WAIT(n)  asm volatile("cp.async.wait_group %0;" :: "n"(n) : "memory")

#define LDSM4(r0,r1,r2,r3,addr) \
    asm volatile("ldmatrix.sync.aligned.m8n8.x4.shared.b16 {%0,%1,%2,%3}, [%4];" \
        : "=r"(r0), "=r"(r1), "=r"(r2), "=r"(r3) : "r"(addr))

#define MMA16816(d, a0,a1,a2,a3, b0,b1) \
    asm volatile("mma.sync.aligned.m16n8k16.row.col.f32.bf16.bf16.f32 " \
        "{%0,%1,%2,%3}, {%4,%5,%6,%7}, {%8,%9}, {%0,%1,%2,%3};" \
        : "+f"((d)[0]), "+f"((d)[1]), "+f"((d)[2]), "+f"((d)[3]) \
        : "r"(a0), "r"(a1), "r"(a2), "r"(a3), "r"(b0), "r"(b1))

__device__ __forceinline__ uint32_t swz(uint32_t o) { return o ^ ((o >> 3) & 0x70); }

__device__ __forceinline__ float act_fn(float h1, int e) {
    if (e == 0) return h1 / (1.0f + expf(-h1));
    if (e == 1) return 0.5f * h1 * (1.0f + erff(h1 * 0.70710678118654752f));
    return fmaxf(h1, 0.0f);
}
__device__ __forceinline__ uint32_t pack_bf2(float a, float b) {
    __nv_bfloat162 t = __halves2bfloat162(__float2bfloat16_rn(a), __float2bfloat16_rn(b));
    return *(uint32_t*)&t;
}

// ============================================================
// Kernel 0: zero per-expert cursors
// ============================================================
__global__ void zero_kernel() {
    if (threadIdx.x < NEXP) g_cursor[threadIdx.x] = 0;
}

// ============================================================
// Kernel 1: gating (one warp per token)
// ============================================================
__global__ void gate_kernel(const float* __restrict__ x,
                            const float* __restrict__ Wg,
                            const float* __restrict__ bg,
                            const float* __restrict__ gu) {
    __shared__ float sWg[HDIM * NEXP];
    int tid = threadIdx.x;
    for (int t = tid; t < HDIM * NEXP; t += blockDim.x) sWg[t] = Wg[t];
    __syncthreads();

    int warp = tid >> 5, lane = tid & 31;
    int n = blockIdx.x * 8 + warp;
    const float* xr = x + (size_t)n * HDIM;

    float a0 = 0.f, a1 = 0.f, a2 = 0.f;
    #pragma unroll 8
    for (int j = 0; j < HDIM; j += 32) {
        float xi = xr[j + lane];
        const float* w = &sWg[(j + lane) * 3];
        a0 += xi * w[0];
        a1 += xi * w[1];
        a2 += xi * w[2];
    }
    #pragma unroll
    for (int off = 16; off > 0; off >>= 1) {
        a0 += __shfl_down_sync(0xffffffffu, a0, off);
        a1 += __shfl_down_sync(0xffffffffu, a1, off);
        a2 += __shfl_down_sync(0xffffffffu, a2, off);
    }
    if (lane == 0) {
        float s[3];
        s[0] = a0 + bg[0];
        s[1] = a1 + bg[1];
        s[2] = a2 + bg[2];
        #pragma unroll
        for (int e = 0; e < 3; e++) {
            float u = gu[(size_t)n * 3 + e];
            u = fminf(fmaxf(u, 1e-6f), 1.0f - 1e-6f);
            s[e] += -logf(-logf(u));
        }
        int best = 0;
        if (s[1] > s[best]) best = 1;
        if (s[2] > s[best]) best = 2;
        int pos = atomicAdd(&g_cursor[best], 1);
        g_idx[best * N_TOK + pos] = n;
    }
}

// ============================================================
// Kernel 2: split x into bf16 hi/lo
// ============================================================
__global__ void xsplit_kernel(const float* __restrict__ x) {
    size_t i = ((size_t)blockIdx.x * 256 + threadIdx.x) * 4;
    float4 v = *(const float4*)(x + i);
    bf16 h0 = __float2bfloat16_rn(v.x);
    bf16 h1 = __float2bfloat16_rn(v.y);
    bf16 h2 = __float2bfloat16_rn(v.z);
    bf16 h3 = __float2bfloat16_rn(v.w);
    bf16 l0 = __float2bfloat16_rn(v.x - __bfloat162float(h0));
    bf16 l1 = __float2bfloat16_rn(v.y - __bfloat162float(h1));
    bf16 l2 = __float2bfloat16_rn(v.z - __bfloat162float(h2));
    bf16 l3 = __float2bfloat16_rn(v.w - __bfloat162float(h3));
    __nv_bfloat162 ha = __halves2bfloat162(h0, h1), hb = __halves2bfloat162(h2, h3);
    __nv_bfloat162 la = __halves2bfloat162(l0, l1), lb = __halves2bfloat162(l2, l3);
    uint2 hq = make_uint2(*(uint32_t*)&ha, *(uint32_t*)&hb);
    uint2 lq = make_uint2(*(uint32_t*)&la, *(uint32_t*)&lb);
    *(uint2*)(g_xhi + i) = hq;
    *(uint2*)(g_xlo + i) = lq;
}

// ============================================================
// Kernel 3: transpose + split weights -> K-major bf16 hi/lo
// ============================================================
__global__ void wsplit_kernel(const float* __restrict__ W1,
                              const float* __restrict__ W3,
                              const float* __restrict__ W2) {
    __shared__ float t[32][33];
    int z = blockIdx.z;
    int mat = z / 3, e = z % 3;
    const float* src;
    bf16 *dh, *dl;
    if (mat == 0)      { src = W1; dh = g_w1hi; dl = g_w1lo; }
    else if (mat == 1) { src = W3; dh = g_w3hi; dl = g_w3lo; }
    else               { src = W2; dh = g_w2hi; dl = g_w2lo; }
    size_t eo = (size_t)e * HDIM * HDIM;
    src += eo; dh += eo; dl += eo;

    int bx = blockIdx.x * 32, by = blockIdx.y * 32;
    int tx = threadIdx.x;
    for (int i = threadIdx.y; i < 32; i += 8)
        t[i][tx] = src[(size_t)(by + i) * HDIM + bx + tx];
    __syncthreads();
    for (int i = threadIdx.y; i < 32; i += 8) {
        float v = t[tx][i];                              // = W[by+tx][bx+i]
        size_t di = (size_t)(bx + i) * HDIM + by + tx;   // Wt[h][d]
        bf16 h = __float2bfloat16_rn(v);
        dh[di] = h;
        dl[di] = __float2bfloat16_rn(v - __bfloat162float(h));
    }
}

// ============================================================
// Kernel 4: pass A — mma.sync dual GEMM (h1, h3) + activation
//   8 warps as 2m x 4n (warp tile 64x32), 4-stage cp.async,
//   single __syncthreads per chunk. grid (8, 512, 3)
// ============================================================
#define A_STAGE 49152
#define A_NST   4
#define A_SMEM  (2048 + A_NST * A_STAGE)

__global__ __launch_bounds__(256, 1)
void passA_mma(const float* __restrict__ b1, const float* __restrict__ b3) {
    int e    = blockIdx.z;
    int cnt  = g_cursor[e];
    int base = blockIdx.y * BM;
    if (base >= cnt) return;
    int n0  = blockIdx.x * BN;
    int tid = threadIdx.x, wid = tid >> 5, lane = tid & 31;
    int m64 = (wid & 1) * 64;        // warp m offset (2 m-groups)
    int n32 = (wid >> 1) * 32;       // warp n offset (4 n-groups)

    extern __shared__ char smem[];
    uint32_t sb = s2u(smem);

    int off = 0;
    for (int i = 0; i < e; i++) off += g_cursor[i];

    int*   srow = (int*)(smem);
    float* sb1  = (float*)(smem + 512);
    float* sb3  = (float*)(smem + 1024);
    if (tid < BM) {
        int p = base + tid;
        srow[tid] = (p < cnt) ? g_idx[e * N_TOK + p] : g_idx[e * N_TOK];
        sb1[tid]  = b1[e * HDIM + n0 + tid];
        sb3[tid]  = b3[e * HDIM + n0 + tid];
    }
    __syncthreads();

    const bf16* w1h = g_w1hi + (size_t)e * HDIM * HDIM;
    const bf16* w1l = g_w1lo + (size_t)e * HDIM * HDIM;
    const bf16* w3h = g_w3hi + (size_t)e * HDIM * HDIM;
    const bf16* w3l = g_w3lo + (size_t)e * HDIM * HDIM;

    // ---- hoisted gather addressing (loop-invariant) ----
    int    rr   = tid >> 3;
    int    cseg = (tid & 7) * 8;          // col within chunk
    size_t aoff[4], boff[4];
    uint32_t ssw[4];
    #pragma unroll
    for (int it = 0; it < 4; it++) {
        int row  = rr + 32 * it;
        aoff[it] = (size_t)srow[row] * HDIM;
        boff[it] = (size_t)(n0 + row) * HDIM;
        ssw[it]  = swz((uint32_t)((row << 7) | ((tid & 7) << 4)));
    }

    auto load_chunk = [&](int c) {
        int st  = c & (A_NST - 1);
        int kk0 = (c & 15) << 6;
        const bf16* As  = (c >= 16 && c < 32) ? g_xlo : g_xhi;
        const bf16* B1s = (c < 32) ? w1h : w1l;
        const bf16* B3s = (c < 32) ? w3h : w3l;
        uint32_t sa = sb + 2048 + st * A_STAGE;
        #pragma unroll
        for (int it = 0; it < 4; it++) {
            cp16(sa + ssw[it],         As  + aoff[it] + kk0 + cseg);
            cp16(sa + 16384 + ssw[it], B1s + boff[it] + kk0 + cseg);
            cp16(sa + 32768 + ssw[it], B3s + boff[it] + kk0 + cseg);
        }
        CP_COMMIT();
    };

    float acc1[4][4][4];
    float acc3[4][4][4];
    #pragma unroll
    for (int i = 0; i < 4; i++)
        #pragma unroll
        for (int j = 0; j < 4; j++)
            #pragma unroll
            for (int q = 0; q < 4; q++) { acc1[i][j][q] = 0.f; acc3[i][j][q] = 0.f; }

    load_chunk(0); load_chunk(1); load_chunk(2);

    for (int c = 0; c < NCH; c++) {
        CP_WAIT(2);
        __syncthreads();
        if (c + 3 < NCH) load_chunk(c + 3);
        else CP_COMMIT();                 // keep group count invariant for CP_WAIT(2)
        uint32_t sa = sb + 2048 + (c & (A_NST - 1)) * A_STAGE;
        #pragma unroll
        for (int kk = 0; kk < 4; kk++) {
            uint32_t a[4][4];
            #pragma unroll
            for (int i = 0; i < 4; i++) {
                int row = m64 + i * 16 + (lane & 15);
                uint32_t o = (uint32_t)(row * 128 + (kk * 2 + (lane >> 4)) * 16);
                LDSM4(a[i][0], a[i][1], a[i][2], a[i][3], sa + swz(o));
            }
            #pragma unroll
            for (int jj = 0; jj < 2; jj++) {
                int nrow = n32 + jj * 16 + ((lane >> 4) << 3) + (lane & 7);
                int half = (lane >> 3) & 1;
                uint32_t sw = swz((uint32_t)(nrow * 128 + (kk * 2 + half) * 16));
                uint32_t b0, b1r, b2r, b3r, c0, c1r, c2r, c3r;
                LDSM4(b0, b1r, b2r, b3r, sa + 16384 + sw);
                LDSM4(c0, c1r, c2r, c3r, sa + 32768 + sw);
                #pragma unroll
                for (int i = 0; i < 4; i++) {
                    MMA16816(acc1[i][2*jj],   a[i][0], a[i][1], a[i][2], a[i][3], b0, b1r);
                    MMA16816(acc1[i][2*jj+1], a[i][0], a[i][1], a[i][2], a[i][3], b2r, b3r);
                    MMA16816(acc3[i][2*jj],   a[i][0], a[i][1], a[i][2], a[i][3], c0, c1r);
                    MMA16816(acc3[i][2*jj+1], a[i][0], a[i][1], a[i][2], a[i][3], c2r, c3r);
                }
            }
        }
    }

    // epilogue: bias + activation, split-bf16 store of inner
    int mrows = cnt - base; if (mrows > BM) mrows = BM;
    #pragma unroll
    for (int i = 0; i < 4; i++) {
        int r0 = m64 + i * 16 + (lane >> 2);
        int r1 = r0 + 8;
        size_t g0 = (size_t)(off + base + r0) * HDIM;
        size_t g1 = (size_t)(off + base + r1) * HDIM;
        #pragma unroll
        for (int j = 0; j < 4; j++) {
            int n = n32 + j * 8 + (lane & 3) * 2;
            float bb1a = sb1[n], bb1b = sb1[n + 1];
            float bb3a = sb3[n], bb3b = sb3[n + 1];
            if (r0 < mrows) {
                float v0 = act_fn(acc1[i][j][0] + bb1a, e) * (acc3[i][j][0] + bb3a);
                float v1 = act_fn(acc1[i][j][1] + bb1b, e) * (acc3[i][j][1] + bb3b);
                bf16 h0 = __float2bfloat16_rn(v0), h1 = __float2bfloat16_rn(v1);
                *(uint32_t*)(g_ihi + g0 + n0 + n) = pack_bf2(v0, v1);
                *(uint32_t*)(g_ilo + g0 + n0 + n) =
                    pack_bf2(v0 - __bfloat162float(h0), v1 - __bfloat162float(h1));
            }
            if (r1 < mrows) {
                float v2 = act_fn(acc1[i][j][2] + bb1a, e) * (acc3[i][j][2] + bb3a);
                float v3 = act_fn(acc1[i][j][3] + bb1b, e) * (acc3[i][j][3] + bb3b);
                bf16 h2 = __float2bfloat16_rn(v2), h3 = __float2bfloat16_rn(v3);
                *(uint32_t*)(g_ihi + g1 + n0 + n) = pack_bf2(v2, v3);
                *(uint32_t*)(g_ilo + g1 + n0 + n) =
                    pack_bf2(v2 - __bfloat162float(h2), v3 - __bfloat162float(h3));
            }
        }
    }
}

// ============================================================
// Kernel 5: pass B — mma.sync GEMM inner@W2 + b2, scatter
//   same structure, single accumulator. grid (8, 512, 3)
// ============================================================
#define B_STAGE 32768
#define B_NST   4
#define B_SMEM  (2048 + B_NST * B_STAGE)

__global__ __launch_bounds__(256, 1)
void passB_mma(const float* __restrict__ b2, float* __restrict__ out) {
    int e    = blockIdx.z;
    int cnt  = g_cursor[e];
    int base = blockIdx.y * BM;
    if (base >= cnt) return;
    int n0  = blockIdx.x * BN;
    int tid = threadIdx.x, wid = tid >> 5, lane = tid & 31;
    int m64 = (wid & 1) * 64;
    int n32 = (wid >> 1) * 32;

    extern __shared__ char smem[];
    uint32_t sb = s2u(smem);

    int off = 0;
    for (int i = 0; i < e; i++) off += g_cursor[i];

    int*   stok = (int*)(smem);
    float* sb2  = (float*)(smem + 512);
    if (tid < BM) {
        int p = base + tid;
        stok[tid] = (p < cnt) ? g_idx[e * N_TOK + p] : 0;
        sb2[tid]  = b2[e * HDIM + n0 + tid];
    }
    __syncthreads();

    const bf16* w2h = g_w2hi + (size_t)e * HDIM * HDIM;
    const bf16* w2l = g_w2lo + (size_t)e * HDIM * HDIM;

    int    rr   = tid >> 3;
    int    cseg = (tid & 7) * 8;
    size_t aoff[4], boff[4];
    uint32_t ssw[4];
    #pragma unroll
    for (int it = 0; it < 4; it++) {
        int row  = rr + 32 * it;
        int arow = (base + row < cnt) ? (off + base + row) : off;
        aoff[it] = (size_t)arow * HDIM;
        boff[it] = (size_t)(n0 + row) * HDIM;
        ssw[it]  = swz((uint32_t)((row << 7) | ((tid & 7) << 4)));
    }

    auto load_chunk = [&](int c) {
        int st  = c & (B_NST - 1);
        int kk0 = (c & 15) << 6;
        const bf16* As = (c >= 16 && c < 32) ? g_ilo : g_ihi;
        const bf16* Bs = (c < 32) ? w2h : w2l;
        uint32_t sa = sb + 2048 + st * B_STAGE;
        #pragma unroll
        for (int it = 0; it < 4; it++) {
            cp16(sa + ssw[it],         As + aoff[it] + kk0 + cseg);
            cp16(sa + 16384 + ssw[it], Bs + boff[it] + kk0 + cseg);
        }
        CP_COMMIT();
    };

    float acc[4][4][4];
    #pragma unroll
    for (int i = 0; i < 4; i++)
        #pragma unroll
        for (int j = 0; j < 4; j++)
            #pragma unroll
            for (int q = 0; q < 4; q++) acc[i][j][q] = 0.f;

    load_chunk(0); load_chunk(1); load_chunk(2);

    for (int c = 0; c < NCH; c++) {
        CP_WAIT(2);
        __syncthreads();
        if (c + 3 < NCH) load_chunk(c + 3);
        else CP_COMMIT();
        uint32_t sa = sb + 2048 + (c & (B_NST - 1)) * B_STAGE;
        #pragma unroll
        for (int kk = 0; kk < 4; kk++) {
            uint32_t a[4][4];
            #pragma unroll
            for (int i = 0; i < 4; i++) {
                int row = m64 + i * 16 + (lane & 15);
                uint32_t o = (uint32_t)(row * 128 + (kk * 2 + (lane >> 4)) * 16);
                LDSM4(a[i][0], a[i][1], a[i][2], a[i][3], sa + swz(o));
            }
            #pragma unroll
            for (int jj = 0; jj < 2; jj++) {
                int nrow = n32 + jj * 16 + ((lane >> 4) << 3) + (lane & 7);
                int half = (lane >> 3) & 1;
                uint32_t sw = swz((uint32_t)(nrow * 128 + (kk * 2 + half) * 16));
                uint32_t b0, b1r, b2r, b3r;
                LDSM4(b0, b1r, b2r, b3r, sa + 16384 + sw);
                #pragma unroll
                for (int i = 0; i < 4; i++) {
                    MMA16816(acc[i][2*jj],   a[i][0], a[i][1], a[i][2], a[i][3], b0, b1r);
                    MMA16816(acc[i][2*jj+1], a[i][0], a[i][1], a[i][2], a[i][3], b2r, b3r);
                }
            }
        }
    }

    int mrows = cnt - base; if (mrows > BM) mrows = BM;
    #pragma unroll
    for (int i = 0; i < 4; i++) {
        int r0 = m64 + i * 16 + (lane >> 2);
        int r1 = r0 + 8;
        float* d0 = out + (size_t)stok[r0] * HDIM + n0;
        float* d1 = out + (size_t)stok[r1 < BM ? r1 : 0] * HDIM + n0;
        #pragma unroll
        for (int j = 0; j < 4; j++) {
            int n = n32 + j * 8 + (lane & 3) * 2;
            float ba = sb2[n], bb = sb2[n + 1];
            if (r0 < mrows) {
                float2 o0 = make_float2(acc[i][j][0] + ba, acc[i][j][1] + bb);
                *(float2*)(d0 + n) = o0;
            }
            if (r1 < mrows) {
                float2 o1 = make_float2(acc[i][j][2] + ba, acc[i][j][3] + bb);
                *(float2*)(d1 + n) = o1;
            }
        }
    }
}

// ============================================================
extern "C" void kernel_launch(void* const* d_in, const int* in_sizes, int n_in,
                              void* d_out, int out_size) {
    (void)in_sizes; (void)n_in; (void)out_size;
    const float* x  = (const float*)d_in[0];
    const float* W1 = (const float*)d_in[1];
    const float* b1 = (const float*)d_in[2];
    const float* W2 = (const float*)d_in[3];
    const float* b2 = (const float*)d_in[4];
    const float* W3 = (const float*)d_in[5];
    const float* b3 = (const float*)d_in[6];
    const float* Wg = (const float*)d_in[7];
    const float* bg = (const float*)d_in[8];
    const float* gu = (const float*)d_in[9];
    float* out = (float*)d_out;

    cudaFuncSetAttribute(passA_mma, cudaFuncAttributeMaxDynamicSharedMemorySize, A_SMEM);
    cudaFuncSetAttribute(passB_mma, cudaFuncAttributeMaxDynamicSharedMemorySize, B_SMEM);

    zero_kernel<<<1, 32>>>();
    gate_kernel<<<N_TOK / 8, 256>>>(x, Wg, bg, gu);
    xsplit_kernel<<<(int)(((size_t)N_TOK * HDIM) / 1024), 256>>>(x);
    {
        dim3 g(32, 32, 9), b(32, 8);
        wsplit_kernel<<<g, b>>>(W1, W3, W2);
    }
    {
        dim3 grid(HDIM / BN, N_TOK / BM, NEXP);
        passA_mma<<<grid, 256, A_SMEM>>>(b1, b3);
        passB_mma<<<grid, 256, B_SMEM>>>(b2, out);
    }
}